// round 6
// baseline (speedup 1.0000x reference)
#include <cuda_runtime.h>
#include <cuda_bf16.h>

#define D 1024
#define THREADS 256
#define WARPS_PER_CTA (THREADS / 32)
#define VEC 8               // float4 chunks per lane per row: D / 4 / 32 = 8
#define EPS 5e-05f

__global__ __launch_bounds__(THREADS, 4)
void qlayernorm_warp_kernel(const float* __restrict__ x,
                            const float* __restrict__ w,
                            const float* __restrict__ b,
                            float* __restrict__ out,
                            int rows)
{
    __shared__ float4 shw[D / 4];
    __shared__ float4 shb[D / 4];

    const int t     = threadIdx.x;
    const int lane  = t & 31;
    const int warp  = t >> 5;
    const int gwarp = blockIdx.x * WARPS_PER_CTA + warp;
    const int total_warps = gridDim.x * WARPS_PER_CTA;

    // Stage weight/bias into shared once per (persistent) CTA.
    shw[t] = reinterpret_cast<const float4*>(w)[t];
    shb[t] = reinterpret_cast<const float4*>(b)[t];
    __syncthreads();

    const float inv_d = 1.0f / (float)D;

    for (int row = gwarp; row < rows; row += total_warps) {
        const float4* __restrict__ xr =
            reinterpret_cast<const float4*>(x + (long long)row * D);
        float4* __restrict__ orow =
            reinterpret_cast<float4*>(out + (long long)row * D);

        // 8 independent streaming LDG.128 per lane — row lives in registers.
        float4 v[VEC];
        #pragma unroll
        for (int i = 0; i < VEC; i++) v[i] = __ldcs(&xr[lane + 32 * i]);

        float s = 0.0f, sq = 0.0f;
        #pragma unroll
        for (int i = 0; i < VEC; i++) {
            s  += v[i].x + v[i].y + v[i].z + v[i].w;
            sq += v[i].x * v[i].x + v[i].y * v[i].y
                + v[i].z * v[i].z + v[i].w * v[i].w;
        }

        // Warp-only reduction: no shared memory, no barrier.
        #pragma unroll
        for (int off = 16; off > 0; off >>= 1) {
            s  += __shfl_xor_sync(0xFFFFFFFFu, s,  off);
            sq += __shfl_xor_sync(0xFFFFFFFFu, sq, off);
        }

        const float mean = s * inv_d;
        const float var  = sq * inv_d - mean * mean;

        // Reference's 4-step loop: _loop(inp,a) = (inp/a + a)*0.5.
        // a/a == 1.0 exactly; remaining divides by a -> multiply by rcp(a).
        const float a  = var + EPS;
        const float r  = __frcp_rn(a);
        const float l1 = (1.0f   + a) * 0.5f;
        const float l2 = (l1 * r + a) * 0.5f;
        const float l3 = (l2 * r + a) * 0.5f;
        const float sd = (l3 * r + a) * 0.5f;
        const float rstd = __frcp_rn(sd);

        #pragma unroll
        for (int i = 0; i < VEC; i++) {
            const float4 wv = shw[lane + 32 * i];
            const float4 bv = shb[lane + 32 * i];
            float4 o;
            o.x = (v[i].x - mean) * rstd * wv.x + bv.x;
            o.y = (v[i].y - mean) * rstd * wv.y + bv.y;
            o.z = (v[i].z - mean) * rstd * wv.z + bv.z;
            o.w = (v[i].w - mean) * rstd * wv.w + bv.w;
            __stcs(&orow[lane + 32 * i], o);
        }
    }
}

extern "C" void kernel_launch(void* const* d_in, const int* in_sizes, int n_in,
                              void* d_out, int out_size)
{
    const float* x = (const float*)d_in[0];
    const float* w = (const float*)d_in[1];
    const float* b = (const float*)d_in[2];
    float* out = (float*)d_out;

    const int rows = in_sizes[0] / D;   // 32768 for B=4, S=8192

    // Persistent: 4 CTAs per SM (148 SMs), warps loop over rows.
    const int grid = 4 * 148;
    qlayernorm_warp_kernel<<<grid, THREADS>>>(x, w, b, out, rows);
}

// round 8
// speedup vs baseline: 1.0052x; 1.0052x over previous
#include <cuda_runtime.h>
#include <cuda_bf16.h>

#define D 1024
#define THREADS 256
#define WARPS_PER_CTA (THREADS / 32)
#define VEC 8               // float4 chunks per lane per row: D / 4 / 32 = 8
#define EPS 5e-05f

__global__ __launch_bounds__(THREADS, 2)
void qlayernorm_warp2_kernel(const float* __restrict__ x,
                             const float* __restrict__ w,
                             const float* __restrict__ b,
                             float* __restrict__ out,
                             int rows)
{
    __shared__ float4 shw[D / 4];
    __shared__ float4 shb[D / 4];

    const int t     = threadIdx.x;
    const int lane  = t & 31;
    const int warp  = t >> 5;
    const int gwarp = blockIdx.x * WARPS_PER_CTA + warp;
    const int total_warps = gridDim.x * WARPS_PER_CTA;

    // Stage weight/bias into shared once per (persistent) CTA.
    shw[t] = reinterpret_cast<const float4*>(w)[t];
    shb[t] = reinterpret_cast<const float4*>(b)[t];
    __syncthreads();

    const float inv_d = 1.0f / (float)D;

    // Each warp owns 2 adjacent rows per iteration. rows is even and the
    // stride is even, so row0+1 is always in range when row0 is.
    for (int row0 = gwarp * 2; row0 < rows; row0 += total_warps * 2) {
        const float4* __restrict__ xr0 =
            reinterpret_cast<const float4*>(x + (long long)row0 * D);
        const float4* __restrict__ xr1 = xr0 + (D / 4);
        float4* __restrict__ or0 =
            reinterpret_cast<float4*>(out + (long long)row0 * D);
        float4* __restrict__ or1 = or0 + (D / 4);

        // Front-batch 16 independent LDG.128 per lane (2 KB in flight/lane).
        float4 va[VEC], vb[VEC];
        #pragma unroll
        for (int i = 0; i < VEC; i++) va[i] = xr0[lane + 32 * i];
        #pragma unroll
        for (int i = 0; i < VEC; i++) vb[i] = xr1[lane + 32 * i];

        float sa = 0.f, qa = 0.f, sb = 0.f, qb = 0.f;
        #pragma unroll
        for (int i = 0; i < VEC; i++) {
            sa += va[i].x + va[i].y + va[i].z + va[i].w;
            qa += va[i].x * va[i].x + va[i].y * va[i].y
                + va[i].z * va[i].z + va[i].w * va[i].w;
            sb += vb[i].x + vb[i].y + vb[i].z + vb[i].w;
            qb += vb[i].x * vb[i].x + vb[i].y * vb[i].y
                + vb[i].z * vb[i].z + vb[i].w * vb[i].w;
        }

        // Two interleaved warp reductions: independent SHFL chains hide
        // each other's latency.
        #pragma unroll
        for (int off = 16; off > 0; off >>= 1) {
            sa += __shfl_xor_sync(0xFFFFFFFFu, sa, off);
            sb += __shfl_xor_sync(0xFFFFFFFFu, sb, off);
            qa += __shfl_xor_sync(0xFFFFFFFFu, qa, off);
            qb += __shfl_xor_sync(0xFFFFFFFFu, qb, off);
        }

        const float mean_a = sa * inv_d;
        const float var_a  = qa * inv_d - mean_a * mean_a;
        const float mean_b = sb * inv_d;
        const float var_b  = qb * inv_d - mean_b * mean_b;

        // Reference's 4-step loop: _loop(inp,a) = (inp/a + a)*0.5.
        // a/a == 1.0 exactly; remaining divides -> multiply by rcp(a).
        const float aa  = var_a + EPS;
        const float ra  = __frcp_rn(aa);
        const float ab  = var_b + EPS;
        const float rb  = __frcp_rn(ab);

        float l_a = (1.0f + aa) * 0.5f;
        float l_b = (1.0f + ab) * 0.5f;
        #pragma unroll
        for (int k = 0; k < 3; k++) {
            l_a = (l_a * ra + aa) * 0.5f;
            l_b = (l_b * rb + ab) * 0.5f;
        }
        const float rstd_a = __frcp_rn(l_a);
        const float rstd_b = __frcp_rn(l_b);

        #pragma unroll
        for (int i = 0; i < VEC; i++) {
            const float4 wv = shw[lane + 32 * i];
            const float4 bv = shb[lane + 32 * i];
            float4 oa, ob;
            oa.x = (va[i].x - mean_a) * rstd_a * wv.x + bv.x;
            oa.y = (va[i].y - mean_a) * rstd_a * wv.y + bv.y;
            oa.z = (va[i].z - mean_a) * rstd_a * wv.z + bv.z;
            oa.w = (va[i].w - mean_a) * rstd_a * wv.w + bv.w;
            ob.x = (vb[i].x - mean_b) * rstd_b * wv.x + bv.x;
            ob.y = (vb[i].y - mean_b) * rstd_b * wv.y + bv.y;
            ob.z = (vb[i].z - mean_b) * rstd_b * wv.z + bv.z;
            ob.w = (vb[i].w - mean_b) * rstd_b * wv.w + bv.w;
            or0[lane + 32 * i] = oa;
            or1[lane + 32 * i] = ob;
        }
    }
}

extern "C" void kernel_launch(void* const* d_in, const int* in_sizes, int n_in,
                              void* d_out, int out_size)
{
    const float* x = (const float*)d_in[0];
    const float* w = (const float*)d_in[1];
    const float* b = (const float*)d_in[2];
    float* out = (float*)d_out;

    const int rows = in_sizes[0] / D;   // 32768 for B=4, S=8192

    // Persistent: 2 CTAs per SM (148 SMs), each warp strides 2 rows/iter.
    const int grid = 2 * 148;
    qlayernorm_warp2_kernel<<<grid, THREADS>>>(x, w, b, out, rows);
}